// round 6
// baseline (speedup 1.0000x reference)
#include <cuda_runtime.h>
#include <cuda_bf16.h>
#include <cuda_fp16.h>
#include <cstdint>

// ============================================================================
// AWAttention on B200, baseline sm_100 mma.sync path.
//   Q = A@Wq^T + bq ; K = X@Wk^T + bk ; S = Q@K^T ; P = softmax(S) ; O = P@X
// GEMM modes:
//   ABM=0: split-bf16 3-MMA (hh+hl+lh)  — Q/K/S (precision-critical)
//   ABM=2: plain fp16 1-MMA             — O (P row-stochastic, near-one-hot)
// OUT modes: 0 = fp32 C ; 1 = split-bf16 (Chi,Clo) epilogue (Q/K);
//            2 = shift-softmax epilogue: E=exp(s-60) fp32 + row-sum atomics (S).
// ============================================================================

#define SWZ(x) ((x) ^ (((x) >> 3) & 0x70))

__device__ __forceinline__ uint32_t smem_u32(const void* p) {
    uint32_t a;
    asm("{ .reg .u64 t; cvta.to.shared.u64 t, %1; cvt.u32.u64 %0, t; }" : "=r"(a) : "l"(p));
    return a;
}

#define CP_ASYNC16(sm, gm) \
    asm volatile("cp.async.cg.shared.global [%0], [%1], 16;" :: "r"(sm), "l"(gm))
#define CP_COMMIT() asm volatile("cp.async.commit_group;" ::: "memory")

__device__ __forceinline__ void ldmx4(uint32_t r[4], uint32_t addr) {
    asm volatile("ldmatrix.sync.aligned.m8n8.x4.shared.b16 {%0,%1,%2,%3}, [%4];"
                 : "=r"(r[0]), "=r"(r[1]), "=r"(r[2]), "=r"(r[3]) : "r"(addr));
}

__device__ __forceinline__ void mma_bf16(float c[4], const uint32_t a[4],
                                         uint32_t b0, uint32_t b1) {
    asm volatile(
        "mma.sync.aligned.m16n8k16.row.col.f32.bf16.bf16.f32 "
        "{%0,%1,%2,%3}, {%4,%5,%6,%7}, {%8,%9}, {%0,%1,%2,%3};"
        : "+f"(c[0]), "+f"(c[1]), "+f"(c[2]), "+f"(c[3])
        : "r"(a[0]), "r"(a[1]), "r"(a[2]), "r"(a[3]), "r"(b0), "r"(b1));
}

__device__ __forceinline__ void mma_f16(float c[4], const uint32_t a[4],
                                        uint32_t b0, uint32_t b1) {
    asm volatile(
        "mma.sync.aligned.m16n8k16.row.col.f32.f16.f16.f32 "
        "{%0,%1,%2,%3}, {%4,%5,%6,%7}, {%8,%9}, {%0,%1,%2,%3};"
        : "+f"(c[0]), "+f"(c[1]), "+f"(c[2]), "+f"(c[3])
        : "r"(a[0]), "r"(a[1]), "r"(a[2]), "r"(a[3]), "r"(b0), "r"(b1));
}

static constexpr int TILE_BYTES = 128 * 128;  // 128 rows x 128B (64 x 16-bit)

// ABM=0: 4 tiles/stage (Ah,Al,Bh,Bl), 3 stages -> 192KB
// ABM=2: 2 tiles/stage (Ah,Bh),       6 stages -> 192KB
template <int ABM> struct Cfg {
    static constexpr int NT  = (ABM == 0) ? 4 : 2;
    static constexpr int STG = (ABM == 0) ? 3 : 6;
    static constexpr int STAGE_B = NT * TILE_BYTES;
    static constexpr int SMEM = STG * STAGE_B;
};

template <int ABM>
__device__ __forceinline__ void load_chunk(
    uint32_t stage, const uint16_t* __restrict__ Ah, const uint16_t* __restrict__ Al,
    const uint16_t* __restrict__ Bh, const uint16_t* __restrict__ Bl,
    int m0, int n0, int kc, int K, int tid)
{
#pragma unroll
    for (int i = 0; i < 4; ++i) {
        int ch  = tid + i * 256;  // 0..1023
        int row = ch >> 3;
        int c16 = ch & 7;
        uint32_t soff = SWZ((uint32_t)(row * 128 + c16 * 16));
        size_t ga = ((size_t)(m0 + row) * K + (size_t)kc * 64) * 2 + (size_t)c16 * 16;
        size_t gb = ((size_t)(n0 + row) * K + (size_t)kc * 64) * 2 + (size_t)c16 * 16;
        if (ABM == 0) {
            CP_ASYNC16(stage + 0 * TILE_BYTES + soff, (const char*)Ah + ga);
            CP_ASYNC16(stage + 1 * TILE_BYTES + soff, (const char*)Al + ga);
            CP_ASYNC16(stage + 2 * TILE_BYTES + soff, (const char*)Bh + gb);
            CP_ASYNC16(stage + 3 * TILE_BYTES + soff, (const char*)Bl + gb);
        } else {
            CP_ASYNC16(stage + 0 * TILE_BYTES + soff, (const char*)Ah + ga);
            CP_ASYNC16(stage + 1 * TILE_BYTES + soff, (const char*)Bh + gb);
        }
    }
}

template <int ABM, int OUTM>
__global__ void __launch_bounds__(256, 1) gemm_kernel(
    const uint16_t* __restrict__ Ah, const uint16_t* __restrict__ Al,
    const uint16_t* __restrict__ Bh, const uint16_t* __restrict__ Bl,
    float* __restrict__ C, __nv_bfloat16* __restrict__ Chi,
    __nv_bfloat16* __restrict__ Clo, float* __restrict__ RS,
    int M, int N, int K, const float* __restrict__ bias)
{
    constexpr int STG = Cfg<ABM>::STG;
    constexpr int STAGE_B = Cfg<ABM>::STAGE_B;

    extern __shared__ __align__(1024) unsigned char smem[];
    uint32_t sbase = smem_u32(smem);
    int tid = threadIdx.x, wid = tid >> 5, lane = tid & 31;
    int warp_m = wid & 1;   // 2 warps over M -> 64 rows
    int warp_n = wid >> 1;  // 4 warps over N -> 32 cols
    int m0 = blockIdx.y * 128, n0 = blockIdx.x * 128;

    float acc[4][4][4];
#pragma unroll
    for (int i = 0; i < 4; ++i)
#pragma unroll
        for (int j = 0; j < 4; ++j)
#pragma unroll
            for (int e = 0; e < 4; ++e) acc[i][j][e] = 0.0f;

    const int nch = K >> 6;

#pragma unroll
    for (int s = 0; s < STG - 1; ++s) {
        if (s < nch)
            load_chunk<ABM>(sbase + s * STAGE_B, Ah, Al, Bh, Bl, m0, n0, s, K, tid);
        CP_COMMIT();
    }

    const int a_rowbase = warp_m * 64 + (lane & 15);
    const int a_colb    = (lane >> 4) * 16;
    const int b_rowbase = warp_n * 32 + (lane & 7) + ((lane >> 3) & 1) * 8;
    const int b_colb    = (lane >> 4) * 16;

    for (int c = 0; c < nch; ++c) {
        if constexpr (STG == 3)      asm volatile("cp.async.wait_group 1;" ::: "memory");
        else if constexpr (STG == 6) asm volatile("cp.async.wait_group 4;" ::: "memory");
        else                         asm volatile("cp.async.wait_group 2;" ::: "memory");
        __syncthreads();

        int nextc = c + STG - 1;
        if (nextc < nch)
            load_chunk<ABM>(sbase + (uint32_t)(nextc % STG) * STAGE_B,
                            Ah, Al, Bh, Bl, m0, n0, nextc, K, tid);
        CP_COMMIT();

        uint32_t st = sbase + (uint32_t)(c % STG) * STAGE_B;

#pragma unroll
        for (int ks = 0; ks < 4; ++ks) {
            if (ABM == 0) {
                uint32_t tAh = st, tAl = st + TILE_BYTES;
                uint32_t tBh = st + 2 * TILE_BYTES, tBl = st + 3 * TILE_BYTES;
                uint32_t ah[4][4], al[4][4];
#pragma unroll
                for (int i = 0; i < 4; ++i) {
                    uint32_t off = SWZ((uint32_t)((a_rowbase + i * 16) * 128 + ks * 32 + a_colb));
                    ldmx4(ah[i], tAh + off);
                    ldmx4(al[i], tAl + off);
                }
                uint32_t bh[4][2], bl[4][2];
#pragma unroll
                for (int jb = 0; jb < 2; ++jb) {
                    uint32_t off = SWZ((uint32_t)((b_rowbase + jb * 16) * 128 + ks * 32 + b_colb));
                    uint32_t r[4];
                    ldmx4(r, tBh + off);
                    bh[jb * 2 + 0][0] = r[0]; bh[jb * 2 + 0][1] = r[2];
                    bh[jb * 2 + 1][0] = r[1]; bh[jb * 2 + 1][1] = r[3];
                    ldmx4(r, tBl + off);
                    bl[jb * 2 + 0][0] = r[0]; bl[jb * 2 + 0][1] = r[2];
                    bl[jb * 2 + 1][0] = r[1]; bl[jb * 2 + 1][1] = r[3];
                }
#pragma unroll
                for (int i = 0; i < 4; ++i)
#pragma unroll
                    for (int j = 0; j < 4; ++j) {
                        mma_bf16(acc[i][j], ah[i], bh[j][0], bh[j][1]);  // hh
                        mma_bf16(acc[i][j], ah[i], bl[j][0], bl[j][1]);  // hl
                        mma_bf16(acc[i][j], al[i], bh[j][0], bh[j][1]);  // lh
                    }
            } else {
                uint32_t tAh = st;
                uint32_t tBh = st + TILE_BYTES;
                uint32_t ah[4][4];
#pragma unroll
                for (int i = 0; i < 4; ++i) {
                    uint32_t off = SWZ((uint32_t)((a_rowbase + i * 16) * 128 + ks * 32 + a_colb));
                    ldmx4(ah[i], tAh + off);
                }
                uint32_t bh[4][2];
#pragma unroll
                for (int jb = 0; jb < 2; ++jb) {
                    uint32_t off = SWZ((uint32_t)((b_rowbase + jb * 16) * 128 + ks * 32 + b_colb));
                    uint32_t r[4];
                    ldmx4(r, tBh + off);
                    bh[jb * 2 + 0][0] = r[0]; bh[jb * 2 + 0][1] = r[2];
                    bh[jb * 2 + 1][0] = r[1]; bh[jb * 2 + 1][1] = r[3];
                }
#pragma unroll
                for (int i = 0; i < 4; ++i)
#pragma unroll
                    for (int j = 0; j < 4; ++j)
                        mma_f16(acc[i][j], ah[i], bh[j][0], bh[j][1]);
            }
        }
        __syncthreads();
    }

    // ------------------------------------------------------------------ epilogue
    int g = lane >> 2, t = lane & 3;

    if constexpr (OUTM == 2) {
        // Shift-softmax: E = exp(s - 60) fp32 + per-row sum atomics.
        // exp(s-60) is fp32-safe: row maxima ~87+-few => E_max ~ e^40 << 3e38,
        // sums >= e^15; terms with s < -27 flush to 0 (true P < 1e-50).
        float* rs_sm = (float*)smem;  // mainloop smem fully consumed after last sync
        if (tid < 128) rs_sm[tid] = 0.0f;
        __syncthreads();
#pragma unroll
        for (int i = 0; i < 4; ++i) {
            int rl0 = warp_m * 64 + i * 16 + g;
            float s0 = 0.0f, s1 = 0.0f;
#pragma unroll
            for (int j = 0; j < 4; ++j) {
                int col = n0 + warp_n * 32 + j * 8 + t * 2;
                float e0 = __expf(acc[i][j][0] - 60.0f);
                float e1 = __expf(acc[i][j][1] - 60.0f);
                float e2 = __expf(acc[i][j][2] - 60.0f);
                float e3 = __expf(acc[i][j][3] - 60.0f);
                *(float2*)(C + (size_t)(m0 + rl0) * N + col)     = make_float2(e0, e1);
                *(float2*)(C + (size_t)(m0 + rl0 + 8) * N + col) = make_float2(e2, e3);
                s0 += e0 + e1;
                s1 += e2 + e3;
            }
            atomicAdd(rs_sm + rl0, s0);
            atomicAdd(rs_sm + rl0 + 8, s1);
        }
        __syncthreads();
        if (tid < 128) atomicAdd(RS + m0 + tid, rs_sm[tid]);
    } else {
#pragma unroll
        for (int i = 0; i < 4; ++i) {
            int r0 = m0 + warp_m * 64 + i * 16 + g;
#pragma unroll
            for (int j = 0; j < 4; ++j) {
                int col = n0 + warp_n * 32 + j * 8 + t * 2;
                float b0 = 0.0f, b1 = 0.0f;
                if (bias) { b0 = __ldg(bias + col); b1 = __ldg(bias + col + 1); }
                float v0 = acc[i][j][0] + b0, v1 = acc[i][j][1] + b1;
                float v2 = acc[i][j][2] + b0, v3 = acc[i][j][3] + b1;
                if constexpr (OUTM == 0) {
                    *(float2*)(C + (size_t)r0 * N + col)       = make_float2(v0, v1);
                    *(float2*)(C + (size_t)(r0 + 8) * N + col) = make_float2(v2, v3);
                } else {
                    __nv_bfloat16 h0 = __float2bfloat16(v0), h1 = __float2bfloat16(v1);
                    __nv_bfloat16 h2 = __float2bfloat16(v2), h3 = __float2bfloat16(v3);
                    __nv_bfloat16 l0 = __float2bfloat16(v0 - __bfloat162float(h0));
                    __nv_bfloat16 l1 = __float2bfloat16(v1 - __bfloat162float(h1));
                    __nv_bfloat16 l2 = __float2bfloat16(v2 - __bfloat162float(h2));
                    __nv_bfloat16 l3 = __float2bfloat16(v3 - __bfloat162float(h3));
                    __nv_bfloat162 hh0; hh0.x = h0; hh0.y = h1;
                    __nv_bfloat162 hh1; hh1.x = h2; hh1.y = h3;
                    __nv_bfloat162 ll0; ll0.x = l0; ll0.y = l1;
                    __nv_bfloat162 ll1; ll1.x = l2; ll1.y = l3;
                    *(__nv_bfloat162*)(Chi + (size_t)r0 * N + col)       = hh0;
                    *(__nv_bfloat162*)(Chi + (size_t)(r0 + 8) * N + col) = hh1;
                    *(__nv_bfloat162*)(Clo + (size_t)r0 * N + col)       = ll0;
                    *(__nv_bfloat162*)(Clo + (size_t)(r0 + 8) * N + col) = ll1;
                }
            }
        }
    }
}

// ---------------------------------------------------------------------------
// Fused fp32 -> (bf16 hi, bf16 lo) split for A, Wq, Wk (one launch)
// ---------------------------------------------------------------------------
__device__ __forceinline__ void split_one(const float* __restrict__ in,
                                          __nv_bfloat16* __restrict__ hi,
                                          __nv_bfloat16* __restrict__ lo,
                                          long long n, long long gtid, long long stride)
{
    for (long long i = gtid; i < n; i += stride) {
        float x = in[i];
        __nv_bfloat16 h = __float2bfloat16(x);
        hi[i] = h;
        lo[i] = __float2bfloat16(x - __bfloat162float(h));
    }
}

__global__ void fused_split_kernel(
    const float* __restrict__ A,  __nv_bfloat16* Ahi,  __nv_bfloat16* Alo,  long long nA,
    const float* __restrict__ W1, __nv_bfloat16* W1hi, __nv_bfloat16* W1lo,
    const float* __restrict__ W2, __nv_bfloat16* W2hi, __nv_bfloat16* W2lo, long long nW)
{
    long long gtid = (long long)blockIdx.x * blockDim.x + threadIdx.x;
    long long stride = (long long)gridDim.x * blockDim.x;
    split_one(A,  Ahi,  Alo,  nA, gtid, stride);
    split_one(W1, W1hi, W1lo, nW, gtid, stride);
    split_one(W2, W2hi, W2lo, nW, gtid, stride);
}

// ---------------------------------------------------------------------------
// X: one read -> (bf16 hi, bf16 lo) linear + fp16 transposed [C,R]
// ---------------------------------------------------------------------------
__global__ void xsplit_kernel(const float* __restrict__ X,
                              __nv_bfloat16* __restrict__ hi,
                              __nv_bfloat16* __restrict__ lo,
                              __half* __restrict__ xt, int R, int C)
{
    __shared__ float tbuf[32][33];
    int c0 = blockIdx.x * 32, r0 = blockIdx.y * 32;
    int tx = threadIdx.x, ty = threadIdx.y;  // 32 x 8
#pragma unroll
    for (int j = 0; j < 4; ++j) {
        int r = r0 + ty + 8 * j;
        float v = X[(long long)r * C + c0 + tx];
        tbuf[ty + 8 * j][tx] = v;
        __nv_bfloat16 h = __float2bfloat16(v);
        hi[(long long)r * C + c0 + tx] = h;
        lo[(long long)r * C + c0 + tx] = __float2bfloat16(v - __bfloat162float(h));
    }
    __syncthreads();
#pragma unroll
    for (int j = 0; j < 4; ++j) {
        float v = tbuf[tx][ty + 8 * j];  // X[r0+tx][c0+ty+8j]
        xt[(long long)(c0 + ty + 8 * j) * R + r0 + tx] = __float2half(v);
    }
}

// ---------------------------------------------------------------------------
// Normalize: P = E * (1/rowsum) -> fp16   (single read of E, no max pass)
// ---------------------------------------------------------------------------
__global__ void __launch_bounds__(256) normalize_kernel(
    const float* __restrict__ E, const float* __restrict__ rs,
    __half* __restrict__ P)
{
    const long long total4 = (long long)8192 * 8192 / 4;
    long long i = (long long)blockIdx.x * blockDim.x + threadIdx.x;
    long long stride = (long long)gridDim.x * blockDim.x;
    for (; i < total4; i += stride) {
        int row = (int)(i >> 11);  // 2048 float4 per 8192-wide row
        float inv = 1.0f / __ldg(rs + row);
        float4 e = __ldg((const float4*)E + i);
        __half2 h0 = __floats2half2_rn(e.x * inv, e.y * inv);
        __half2 h1 = __floats2half2_rn(e.z * inv, e.w * inv);
        ((__half2*)P)[i * 2 + 0] = h0;
        ((__half2*)P)[i * 2 + 1] = h1;
    }
}

// ---------------------------------------------------------------------------
// Scratch
// ---------------------------------------------------------------------------
static constexpr size_t SZ_AX = (size_t)8192 * 1024;
static constexpr size_t SZ_W  = (size_t)512 * 1024;
static constexpr size_t SZ_QK = (size_t)8192 * 512;
static constexpr size_t SZ_S  = (size_t)8192 * 8192;

static constexpr size_t OFF_AHI  = 0;
static constexpr size_t OFF_ALO  = OFF_AHI  + SZ_AX * 2;
static constexpr size_t OFF_XHI  = OFF_ALO  + SZ_AX * 2;
static constexpr size_t OFF_XLO  = OFF_XHI  + SZ_AX * 2;
static constexpr size_t OFF_WQHI = OFF_XLO  + SZ_AX * 2;
static constexpr size_t OFF_WQLO = OFF_WQHI + SZ_W * 2;
static constexpr size_t OFF_WKHI = OFF_WQLO + SZ_W * 2;
static constexpr size_t OFF_WKLO = OFF_WKHI + SZ_W * 2;
static constexpr size_t OFF_QHI  = OFF_WKLO + SZ_W * 2;
static constexpr size_t OFF_QLO  = OFF_QHI  + SZ_QK * 2;
static constexpr size_t OFF_KHI  = OFF_QLO  + SZ_QK * 2;
static constexpr size_t OFF_KLO  = OFF_KHI  + SZ_QK * 2;
static constexpr size_t OFF_E    = OFF_KLO  + SZ_QK * 2;
static constexpr size_t OFF_PHI  = OFF_E    + SZ_S * 4;
static constexpr size_t OFF_XTHI = OFF_PHI  + SZ_S * 2;
static constexpr size_t OFF_RS   = OFF_XTHI + SZ_AX * 2;
static constexpr size_t SCRATCH_TOTAL = OFF_RS + 8192 * 4;

__device__ __align__(256) unsigned char g_scratch[SCRATCH_TOTAL];

// ---------------------------------------------------------------------------
// kernel_launch
// ---------------------------------------------------------------------------
extern "C" void kernel_launch(void* const* d_in, const int* in_sizes, int n_in,
                              void* d_out, int out_size)
{
    const float* A  = (const float*)d_in[0];
    const float* X  = (const float*)d_in[1];
    const float* Wq = (const float*)d_in[2];
    const float* bq = (const float*)d_in[3];
    const float* Wk = (const float*)d_in[4];
    const float* bk = (const float*)d_in[5];
    float* out = (float*)d_out;

    unsigned char* s = nullptr;
    cudaGetSymbolAddress((void**)&s, g_scratch);
    auto BF = [&](size_t off) { return (__nv_bfloat16*)(s + off); };
    auto U16 = [&](size_t off) { return (const uint16_t*)(s + off); };
    auto F  = [&](size_t off) { return (float*)(s + off); };

    cudaFuncSetAttribute(gemm_kernel<0, 1>,
                         cudaFuncAttributeMaxDynamicSharedMemorySize, Cfg<0>::SMEM);
    cudaFuncSetAttribute(gemm_kernel<0, 2>,
                         cudaFuncAttributeMaxDynamicSharedMemorySize, Cfg<0>::SMEM);
    cudaFuncSetAttribute(gemm_kernel<2, 0>,
                         cudaFuncAttributeMaxDynamicSharedMemorySize, Cfg<2>::SMEM);

    // Zero row-sum accumulator (replayed each graph launch)
    cudaMemsetAsync(s + OFF_RS, 0, 8192 * sizeof(float));

    // Splits: A/Wq/Wk (one launch) ; X -> hi/lo + fp16 transpose (one launch)
    fused_split_kernel<<<2048, 256>>>(
        A,  BF(OFF_AHI),  BF(OFF_ALO),  (long long)SZ_AX,
        Wq, BF(OFF_WQHI), BF(OFF_WQLO),
        Wk, BF(OFF_WKHI), BF(OFF_WKLO), (long long)SZ_W);
    xsplit_kernel<<<dim3(1024 / 32, 8192 / 32), dim3(32, 8)>>>(
        X, BF(OFF_XHI), BF(OFF_XLO), (__half*)(s + OFF_XTHI), 8192, 1024);

    // Q/K GEMMs with fused split-bf16 epilogue (M=8192, N=512, K=1024)
    dim3 gq(512 / 128, 8192 / 128);
    gemm_kernel<0, 1><<<gq, 256, Cfg<0>::SMEM>>>(
        U16(OFF_AHI), U16(OFF_ALO), U16(OFF_WQHI), U16(OFF_WQLO),
        nullptr, BF(OFF_QHI), BF(OFF_QLO), nullptr, 8192, 512, 1024, bq);
    gemm_kernel<0, 1><<<gq, 256, Cfg<0>::SMEM>>>(
        U16(OFF_XHI), U16(OFF_XLO), U16(OFF_WKHI), U16(OFF_WKLO),
        nullptr, BF(OFF_KHI), BF(OFF_KLO), nullptr, 8192, 512, 1024, bk);

    // S GEMM with fused exp + row-sum epilogue (M=8192, N=8192, K=512)
    dim3 gs(8192 / 128, 8192 / 128);
    gemm_kernel<0, 2><<<gs, 256, Cfg<0>::SMEM>>>(
        U16(OFF_QHI), U16(OFF_QLO), U16(OFF_KHI), U16(OFF_KLO),
        F(OFF_E), nullptr, nullptr, F(OFF_RS), 8192, 8192, 512, nullptr);

    // P = E / rowsum -> fp16
    normalize_kernel<<<8192, 256>>>(F(OFF_E), F(OFF_RS), (__half*)(s + OFF_PHI));

    // O = P @ X   (M=8192, N=1024, K=8192), single fp16 MMA
    dim3 go(1024 / 128, 8192 / 128);
    gemm_kernel<2, 0><<<go, 256, Cfg<2>::SMEM>>>(
        U16(OFF_PHI), nullptr, U16(OFF_XTHI), nullptr,
        out, nullptr, nullptr, nullptr, 8192, 1024, 8192, nullptr);
}

// round 7
// speedup vs baseline: 1.0449x; 1.0449x over previous
#include <cuda_runtime.h>
#include <cuda_bf16.h>
#include <cuda_fp16.h>
#include <cstdint>

// ============================================================================
// AWAttention on B200, baseline sm_100 mma.sync path.
//   Q = A@Wq^T + bq ; K = X@Wk^T + bk ; S = Q@K^T ; P = softmax(S) ; O = P@X
// GEMM: 512 threads / 16 warps, 128x128 CTA tile, 32x32 warp tiles.
//   ABM=0: split-bf16 3-MMA (hh+hl+lh)  — Q/K/S (precision-critical)
//   ABM=2: plain fp16 1-MMA             — O (P row-stochastic, near-one-hot)
// OUT modes: 0 = fp32 C ; 1 = split-bf16 (Chi,Clo) epilogue (Q/K).
// ============================================================================

#define SWZ(x) ((x) ^ (((x) >> 3) & 0x70))

__device__ __forceinline__ uint32_t smem_u32(const void* p) {
    uint32_t a;
    asm("{ .reg .u64 t; cvta.to.shared.u64 t, %1; cvt.u32.u64 %0, t; }" : "=r"(a) : "l"(p));
    return a;
}

#define CP_ASYNC16(sm, gm) \
    asm volatile("cp.async.cg.shared.global [%0], [%1], 16;" :: "r"(sm), "l"(gm))
#define CP_COMMIT() asm volatile("cp.async.commit_group;" ::: "memory")

__device__ __forceinline__ void ldmx4(uint32_t r[4], uint32_t addr) {
    asm volatile("ldmatrix.sync.aligned.m8n8.x4.shared.b16 {%0,%1,%2,%3}, [%4];"
                 : "=r"(r[0]), "=r"(r[1]), "=r"(r[2]), "=r"(r[3]) : "r"(addr));
}

__device__ __forceinline__ void mma_bf16(float c[4], const uint32_t a[4],
                                         uint32_t b0, uint32_t b1) {
    asm volatile(
        "mma.sync.aligned.m16n8k16.row.col.f32.bf16.bf16.f32 "
        "{%0,%1,%2,%3}, {%4,%5,%6,%7}, {%8,%9}, {%0,%1,%2,%3};"
        : "+f"(c[0]), "+f"(c[1]), "+f"(c[2]), "+f"(c[3])
        : "r"(a[0]), "r"(a[1]), "r"(a[2]), "r"(a[3]), "r"(b0), "r"(b1));
}

__device__ __forceinline__ void mma_f16(float c[4], const uint32_t a[4],
                                        uint32_t b0, uint32_t b1) {
    asm volatile(
        "mma.sync.aligned.m16n8k16.row.col.f32.f16.f16.f32 "
        "{%0,%1,%2,%3}, {%4,%5,%6,%7}, {%8,%9}, {%0,%1,%2,%3};"
        : "+f"(c[0]), "+f"(c[1]), "+f"(c[2]), "+f"(c[3])
        : "r"(a[0]), "r"(a[1]), "r"(a[2]), "r"(a[3]), "r"(b0), "r"(b1));
}

static constexpr int TILE_BYTES = 128 * 128;  // 128 rows x 128B (64 x 16-bit)

// ABM=0: 4 tiles/stage (Ah,Al,Bh,Bl), 3 stages -> 192KB
// ABM=2: 2 tiles/stage (Ah,Bh),       6 stages -> 192KB
template <int ABM> struct Cfg {
    static constexpr int NT  = (ABM == 0) ? 4 : 2;
    static constexpr int STG = (ABM == 0) ? 3 : 6;
    static constexpr int STAGE_B = NT * TILE_BYTES;
    static constexpr int SMEM = STG * STAGE_B;
};

template <int ABM>
__device__ __forceinline__ void load_chunk(
    uint32_t stage, const uint16_t* __restrict__ Ah, const uint16_t* __restrict__ Al,
    const uint16_t* __restrict__ Bh, const uint16_t* __restrict__ Bl,
    int m0, int n0, int kc, int K, int tid)
{
#pragma unroll
    for (int i = 0; i < 2; ++i) {
        int ch  = tid + i * 512;  // 0..1023
        int row = ch >> 3;
        int c16 = ch & 7;
        uint32_t soff = SWZ((uint32_t)(row * 128 + c16 * 16));
        size_t ga = ((size_t)(m0 + row) * K + (size_t)kc * 64) * 2 + (size_t)c16 * 16;
        size_t gb = ((size_t)(n0 + row) * K + (size_t)kc * 64) * 2 + (size_t)c16 * 16;
        if (ABM == 0) {
            CP_ASYNC16(stage + 0 * TILE_BYTES + soff, (const char*)Ah + ga);
            CP_ASYNC16(stage + 1 * TILE_BYTES + soff, (const char*)Al + ga);
            CP_ASYNC16(stage + 2 * TILE_BYTES + soff, (const char*)Bh + gb);
            CP_ASYNC16(stage + 3 * TILE_BYTES + soff, (const char*)Bl + gb);
        } else {
            CP_ASYNC16(stage + 0 * TILE_BYTES + soff, (const char*)Ah + ga);
            CP_ASYNC16(stage + 1 * TILE_BYTES + soff, (const char*)Bh + gb);
        }
    }
}

template <int ABM, int OUTM>
__global__ void __launch_bounds__(512, 1) gemm_kernel(
    const uint16_t* __restrict__ Ah, const uint16_t* __restrict__ Al,
    const uint16_t* __restrict__ Bh, const uint16_t* __restrict__ Bl,
    float* __restrict__ C, __nv_bfloat16* __restrict__ Chi,
    __nv_bfloat16* __restrict__ Clo, int M, int N, int K,
    const float* __restrict__ bias)
{
    constexpr int STG = Cfg<ABM>::STG;
    constexpr int STAGE_B = Cfg<ABM>::STAGE_B;

    extern __shared__ __align__(1024) unsigned char smem[];
    uint32_t sbase = smem_u32(smem);
    int tid = threadIdx.x, wid = tid >> 5, lane = tid & 31;
    int warp_m = wid & 3;   // 4 warps over M -> 32 rows each
    int warp_n = wid >> 2;  // 4 warps over N -> 32 cols each
    int m0 = blockIdx.y * 128, n0 = blockIdx.x * 128;

    float acc[2][4][4];  // [mtile(16)][ntile(8)][frag]
#pragma unroll
    for (int i = 0; i < 2; ++i)
#pragma unroll
        for (int j = 0; j < 4; ++j)
#pragma unroll
            for (int e = 0; e < 4; ++e) acc[i][j][e] = 0.0f;

    const int nch = K >> 6;

#pragma unroll
    for (int s = 0; s < STG - 1; ++s) {
        if (s < nch)
            load_chunk<ABM>(sbase + s * STAGE_B, Ah, Al, Bh, Bl, m0, n0, s, K, tid);
        CP_COMMIT();
    }

    const int a_rowbase = warp_m * 32 + (lane & 15);
    const int a_colb    = (lane >> 4) * 16;
    const int b_rowbase = warp_n * 32 + (lane & 7) + ((lane >> 3) & 1) * 8;
    const int b_colb    = (lane >> 4) * 16;

    for (int c = 0; c < nch; ++c) {
        if constexpr (STG == 3)      asm volatile("cp.async.wait_group 1;" ::: "memory");
        else if constexpr (STG == 6) asm volatile("cp.async.wait_group 4;" ::: "memory");
        else                         asm volatile("cp.async.wait_group 2;" ::: "memory");
        __syncthreads();

        int nextc = c + STG - 1;
        if (nextc < nch)
            load_chunk<ABM>(sbase + (uint32_t)(nextc % STG) * STAGE_B,
                            Ah, Al, Bh, Bl, m0, n0, nextc, K, tid);
        CP_COMMIT();

        uint32_t st = sbase + (uint32_t)(c % STG) * STAGE_B;

#pragma unroll
        for (int ks = 0; ks < 4; ++ks) {
            if (ABM == 0) {
                uint32_t tAh = st, tAl = st + TILE_BYTES;
                uint32_t tBh = st + 2 * TILE_BYTES, tBl = st + 3 * TILE_BYTES;
                uint32_t ah[2][4], al[2][4];
#pragma unroll
                for (int i = 0; i < 2; ++i) {
                    uint32_t off = SWZ((uint32_t)((a_rowbase + i * 16) * 128 + ks * 32 + a_colb));
                    ldmx4(ah[i], tAh + off);
                    ldmx4(al[i], tAl + off);
                }
                uint32_t bh[4][2], bl[4][2];
#pragma unroll
                for (int jb = 0; jb < 2; ++jb) {
                    uint32_t off = SWZ((uint32_t)((b_rowbase + jb * 16) * 128 + ks * 32 + b_colb));
                    uint32_t r[4];
                    ldmx4(r, tBh + off);
                    bh[jb * 2 + 0][0] = r[0]; bh[jb * 2 + 0][1] = r[2];
                    bh[jb * 2 + 1][0] = r[1]; bh[jb * 2 + 1][1] = r[3];
                    ldmx4(r, tBl + off);
                    bl[jb * 2 + 0][0] = r[0]; bl[jb * 2 + 0][1] = r[2];
                    bl[jb * 2 + 1][0] = r[1]; bl[jb * 2 + 1][1] = r[3];
                }
#pragma unroll
                for (int i = 0; i < 2; ++i)
#pragma unroll
                    for (int j = 0; j < 4; ++j) {
                        mma_bf16(acc[i][j], ah[i], bh[j][0], bh[j][1]);  // hh
                        mma_bf16(acc[i][j], ah[i], bl[j][0], bl[j][1]);  // hl
                        mma_bf16(acc[i][j], al[i], bh[j][0], bh[j][1]);  // lh
                    }
            } else {
                uint32_t tAh = st;
                uint32_t tBh = st + TILE_BYTES;
                uint32_t ah[2][4];
#pragma unroll
                for (int i = 0; i < 2; ++i) {
                    uint32_t off = SWZ((uint32_t)((a_rowbase + i * 16) * 128 + ks * 32 + a_colb));
                    ldmx4(ah[i], tAh + off);
                }
                uint32_t bh[4][2];
#pragma unroll
                for (int jb = 0; jb < 2; ++jb) {
                    uint32_t off = SWZ((uint32_t)((b_rowbase + jb * 16) * 128 + ks * 32 + b_colb));
                    uint32_t r[4];
                    ldmx4(r, tBh + off);
                    bh[jb * 2 + 0][0] = r[0]; bh[jb * 2 + 0][1] = r[2];
                    bh[jb * 2 + 1][0] = r[1]; bh[jb * 2 + 1][1] = r[3];
                }
#pragma unroll
                for (int i = 0; i < 2; ++i)
#pragma unroll
                    for (int j = 0; j < 4; ++j)
                        mma_f16(acc[i][j], ah[i], bh[j][0], bh[j][1]);
            }
        }
        __syncthreads();
    }

    // Epilogue
    int g = lane >> 2, t = lane & 3;
#pragma unroll
    for (int i = 0; i < 2; ++i) {
        int r0 = m0 + warp_m * 32 + i * 16 + g;
#pragma unroll
        for (int j = 0; j < 4; ++j) {
            int col = n0 + warp_n * 32 + j * 8 + t * 2;
            float b0 = 0.0f, b1 = 0.0f;
            if (bias) { b0 = __ldg(bias + col); b1 = __ldg(bias + col + 1); }
            float v0 = acc[i][j][0] + b0, v1 = acc[i][j][1] + b1;
            float v2 = acc[i][j][2] + b0, v3 = acc[i][j][3] + b1;
            if constexpr (OUTM == 0) {
                *(float2*)(C + (size_t)r0 * N + col)       = make_float2(v0, v1);
                *(float2*)(C + (size_t)(r0 + 8) * N + col) = make_float2(v2, v3);
            } else {
                __nv_bfloat16 h0 = __float2bfloat16(v0), h1 = __float2bfloat16(v1);
                __nv_bfloat16 h2 = __float2bfloat16(v2), h3 = __float2bfloat16(v3);
                __nv_bfloat16 l0 = __float2bfloat16(v0 - __bfloat162float(h0));
                __nv_bfloat16 l1 = __float2bfloat16(v1 - __bfloat162float(h1));
                __nv_bfloat16 l2 = __float2bfloat16(v2 - __bfloat162float(h2));
                __nv_bfloat16 l3 = __float2bfloat16(v3 - __bfloat162float(h3));
                __nv_bfloat162 hh0; hh0.x = h0; hh0.y = h1;
                __nv_bfloat162 hh1; hh1.x = h2; hh1.y = h3;
                __nv_bfloat162 ll0; ll0.x = l0; ll0.y = l1;
                __nv_bfloat162 ll1; ll1.x = l2; ll1.y = l3;
                *(__nv_bfloat162*)(Chi + (size_t)r0 * N + col)       = hh0;
                *(__nv_bfloat162*)(Chi + (size_t)(r0 + 8) * N + col) = hh1;
                *(__nv_bfloat162*)(Clo + (size_t)r0 * N + col)       = ll0;
                *(__nv_bfloat162*)(Clo + (size_t)(r0 + 8) * N + col) = ll1;
            }
        }
    }
}

// ---------------------------------------------------------------------------
// Fused fp32 -> (bf16 hi, bf16 lo) split for A, Wq, Wk (one launch)
// ---------------------------------------------------------------------------
__device__ __forceinline__ void split_one(const float* __restrict__ in,
                                          __nv_bfloat16* __restrict__ hi,
                                          __nv_bfloat16* __restrict__ lo,
                                          long long n, long long gtid, long long stride)
{
    for (long long i = gtid; i < n; i += stride) {
        float x = in[i];
        __nv_bfloat16 h = __float2bfloat16(x);
        hi[i] = h;
        lo[i] = __float2bfloat16(x - __bfloat162float(h));
    }
}

__global__ void fused_split_kernel(
    const float* __restrict__ A,  __nv_bfloat16* Ahi,  __nv_bfloat16* Alo,  long long nA,
    const float* __restrict__ W1, __nv_bfloat16* W1hi, __nv_bfloat16* W1lo,
    const float* __restrict__ W2, __nv_bfloat16* W2hi, __nv_bfloat16* W2lo, long long nW)
{
    long long gtid = (long long)blockIdx.x * blockDim.x + threadIdx.x;
    long long stride = (long long)gridDim.x * blockDim.x;
    split_one(A,  Ahi,  Alo,  nA, gtid, stride);
    split_one(W1, W1hi, W1lo, nW, gtid, stride);
    split_one(W2, W2hi, W2lo, nW, gtid, stride);
}

// ---------------------------------------------------------------------------
// X: one read -> (bf16 hi, bf16 lo) linear + fp16 transposed [C,R]
// ---------------------------------------------------------------------------
__global__ void xsplit_kernel(const float* __restrict__ X,
                              __nv_bfloat16* __restrict__ hi,
                              __nv_bfloat16* __restrict__ lo,
                              __half* __restrict__ xt, int R, int C)
{
    __shared__ float tbuf[32][33];
    int c0 = blockIdx.x * 32, r0 = blockIdx.y * 32;
    int tx = threadIdx.x, ty = threadIdx.y;  // 32 x 8
#pragma unroll
    for (int j = 0; j < 4; ++j) {
        int r = r0 + ty + 8 * j;
        float v = X[(long long)r * C + c0 + tx];
        tbuf[ty + 8 * j][tx] = v;
        __nv_bfloat16 h = __float2bfloat16(v);
        hi[(long long)r * C + c0 + tx] = h;
        lo[(long long)r * C + c0 + tx] = __float2bfloat16(v - __bfloat162float(h));
    }
    __syncthreads();
#pragma unroll
    for (int j = 0; j < 4; ++j) {
        float v = tbuf[tx][ty + 8 * j];  // X[r0+tx][c0+ty+8j]
        xt[(long long)(c0 + ty + 8 * j) * R + r0 + tx] = __float2half(v);
    }
}

// ---------------------------------------------------------------------------
// Row softmax (N=8192) writing fp16 probabilities (single S read via smem buf)
// ---------------------------------------------------------------------------
__global__ void __launch_bounds__(256) softmax_kernel(
    const float* __restrict__ S, __half* __restrict__ P, int N)
{
    __shared__ float buf[8192];
    __shared__ float red[8];
    int row = blockIdx.x, tid = threadIdx.x;
    const float* s = S + (long long)row * N;

    float mx = -3.0e38f;
    for (int i = tid; i < N; i += 256) mx = fmaxf(mx, s[i]);
#pragma unroll
    for (int o = 16; o; o >>= 1) mx = fmaxf(mx, __shfl_xor_sync(0xFFFFFFFFu, mx, o));
    if ((tid & 31) == 0) red[tid >> 5] = mx;
    __syncthreads();
    mx = red[0];
#pragma unroll
    for (int w = 1; w < 8; ++w) mx = fmaxf(mx, red[w]);

    float sum = 0.0f;
    for (int i = tid; i < N; i += 256) {
        float e = __expf(s[i] - mx);
        buf[i] = e;
        sum += e;
    }
#pragma unroll
    for (int o = 16; o; o >>= 1) sum += __shfl_xor_sync(0xFFFFFFFFu, sum, o);
    __syncthreads();
    if ((tid & 31) == 0) red[tid >> 5] = sum;
    __syncthreads();
    sum = 0.0f;
#pragma unroll
    for (int w = 0; w < 8; ++w) sum += red[w];
    float inv = 1.0f / sum;

    for (int i = tid; i < N; i += 256)
        P[(long long)row * N + i] = __float2half(buf[i] * inv);
}

// ---------------------------------------------------------------------------
// Scratch
// ---------------------------------------------------------------------------
static constexpr size_t SZ_AX = (size_t)8192 * 1024;
static constexpr size_t SZ_W  = (size_t)512 * 1024;
static constexpr size_t SZ_QK = (size_t)8192 * 512;
static constexpr size_t SZ_S  = (size_t)8192 * 8192;

static constexpr size_t OFF_AHI  = 0;
static constexpr size_t OFF_ALO  = OFF_AHI  + SZ_AX * 2;
static constexpr size_t OFF_XHI  = OFF_ALO  + SZ_AX * 2;
static constexpr size_t OFF_XLO  = OFF_XHI  + SZ_AX * 2;
static constexpr size_t OFF_WQHI = OFF_XLO  + SZ_AX * 2;
static constexpr size_t OFF_WQLO = OFF_WQHI + SZ_W * 2;
static constexpr size_t OFF_WKHI = OFF_WQLO + SZ_W * 2;
static constexpr size_t OFF_WKLO = OFF_WKHI + SZ_W * 2;
static constexpr size_t OFF_QHI  = OFF_WKLO + SZ_W * 2;
static constexpr size_t OFF_QLO  = OFF_QHI  + SZ_QK * 2;
static constexpr size_t OFF_KHI  = OFF_QLO  + SZ_QK * 2;
static constexpr size_t OFF_KLO  = OFF_KHI  + SZ_QK * 2;
static constexpr size_t OFF_S    = OFF_KLO  + SZ_QK * 2;
static constexpr size_t OFF_PHI  = OFF_S    + SZ_S * 4;
static constexpr size_t OFF_XTHI = OFF_PHI  + SZ_S * 2;
static constexpr size_t SCRATCH_TOTAL = OFF_XTHI + SZ_AX * 2;

__device__ __align__(256) unsigned char g_scratch[SCRATCH_TOTAL];

// ---------------------------------------------------------------------------
// kernel_launch
// ---------------------------------------------------------------------------
extern "C" void kernel_launch(void* const* d_in, const int* in_sizes, int n_in,
                              void* d_out, int out_size)
{
    const float* A  = (const float*)d_in[0];
    const float* X  = (const float*)d_in[1];
    const float* Wq = (const float*)d_in[2];
    const float* bq = (const float*)d_in[3];
    const float* Wk = (const float*)d_in[4];
    const float* bk = (const float*)d_in[5];
    float* out = (float*)d_out;

    unsigned char* s = nullptr;
    cudaGetSymbolAddress((void**)&s, g_scratch);
    auto BF = [&](size_t off) { return (__nv_bfloat16*)(s + off); };
    auto U16 = [&](size_t off) { return (const uint16_t*)(s + off); };
    auto F  = [&](size_t off) { return (float*)(s + off); };

    cudaFuncSetAttribute(gemm_kernel<0, 0>,
                         cudaFuncAttributeMaxDynamicSharedMemorySize, Cfg<0>::SMEM);
    cudaFuncSetAttribute(gemm_kernel<0, 1>,
                         cudaFuncAttributeMaxDynamicSharedMemorySize, Cfg<0>::SMEM);
    cudaFuncSetAttribute(gemm_kernel<2, 0>,
                         cudaFuncAttributeMaxDynamicSharedMemorySize, Cfg<2>::SMEM);

    // Splits: A/Wq/Wk (one launch) ; X -> hi/lo + fp16 transpose (one launch)
    fused_split_kernel<<<2048, 256>>>(
        A,  BF(OFF_AHI),  BF(OFF_ALO),  (long long)SZ_AX,
        Wq, BF(OFF_WQHI), BF(OFF_WQLO),
        Wk, BF(OFF_WKHI), BF(OFF_WKLO), (long long)SZ_W);
    xsplit_kernel<<<dim3(1024 / 32, 8192 / 32), dim3(32, 8)>>>(
        X, BF(OFF_XHI), BF(OFF_XLO), (__half*)(s + OFF_XTHI), 8192, 1024);

    // Q/K GEMMs with fused split-bf16 epilogue (M=8192, N=512, K=1024)
    dim3 gq(512 / 128, 8192 / 128);
    gemm_kernel<0, 1><<<gq, 512, Cfg<0>::SMEM>>>(
        U16(OFF_AHI), U16(OFF_ALO), U16(OFF_WQHI), U16(OFF_WQLO),
        nullptr, BF(OFF_QHI), BF(OFF_QLO), 8192, 512, 1024, bq);
    gemm_kernel<0, 1><<<gq, 512, Cfg<0>::SMEM>>>(
        U16(OFF_XHI), U16(OFF_XLO), U16(OFF_WKHI), U16(OFF_WKLO),
        nullptr, BF(OFF_KHI), BF(OFF_KLO), 8192, 512, 1024, bk);

    // S = Q @ K^T   (M=8192, N=8192, K=512)
    dim3 gs(8192 / 128, 8192 / 128);
    gemm_kernel<0, 0><<<gs, 512, Cfg<0>::SMEM>>>(
        U16(OFF_QHI), U16(OFF_QLO), U16(OFF_KHI), U16(OFF_KLO),
        F(OFF_S), nullptr, nullptr, 8192, 8192, 512, nullptr);

    // P = softmax(S) -> fp16
    softmax_kernel<<<8192, 256>>>(F(OFF_S), (__half*)(s + OFF_PHI), 8192);

    // O = P @ X   (M=8192, N=1024, K=8192), single fp16 MMA
    dim3 go(1024 / 128, 8192 / 128);
    gemm_kernel<2, 0><<<go, 512, Cfg<2>::SMEM>>>(
        U16(OFF_PHI), nullptr, U16(OFF_XTHI), nullptr,
        out, nullptr, nullptr, 8192, 1024, 8192, nullptr);
}